// round 3
// baseline (speedup 1.0000x reference)
#include <cuda_runtime.h>
#include <math.h>
#include <stdint.h>
#include <stddef.h>

// ---------------- problem dims ----------------
#define B_    64
#define N_    4096
#define DIN_  256
#define K_    8
#define D_    256
#define H_    512
#define BK_   512            // B_*K_
#define SCALE_ 0.0625f       // D^-0.5
#define EPSLN 1e-5f
#define EPSA  1e-8f

// ---------------- device scratch (static, no allocs) ----------------
__device__ __align__(16) float g_xn[(size_t)B_ * N_ * DIN_];   // 268 MB: layernormed inputs
__device__ __align__(16) float g_attn[(size_t)B_ * N_ * K_];   // [B][N][8] softmax
__device__ __align__(16) float g_slots[BK_ * D_];
__device__ __align__(16) float g_sn[BK_ * D_];
__device__ __align__(16) float g_qt[BK_ * DIN_];
__device__ float g_qb[BK_];
__device__ float g_S[BK_];
__device__ __align__(16) float g_U[BK_ * DIN_];
__device__ __align__(16) float g_un[BK_ * DIN_];
__device__ float g_snorm[BK_];
__device__ __align__(16) float g_updates[BK_ * D_];
__device__ __align__(16) float g_gi[BK_ * 3 * D_];
__device__ __align__(16) float g_gh[BK_ * 3 * D_];
__device__ __align__(16) float g_h[BK_ * D_];
__device__ __align__(16) float g_ff[BK_ * D_];
__device__ __align__(16) float g_f1[BK_ * H_];
__device__ __align__(16) float g_Wqk[D_ * DIN_];   // scale * Wq^T @ Wk   [j][i]
__device__ float g_bqk[DIN_];                      // scale * bq @ Wk
__device__ float g_wb[D_];                         // scale * Wq^T @ bk
__device__ float g_c0;                             // scale * bq.bk
__device__ __align__(16) float g_WihT[D_ * 3 * D_];
__device__ __align__(16) float g_WhhT[D_ * 3 * D_];
__device__ __align__(16) float g_WvT[DIN_ * D_];
__device__ __align__(16) float g_W1T[D_ * H_];
__device__ __align__(16) float g_W2T[H_ * D_];

// ---------------- helpers ----------------
__device__ __forceinline__ void blockReduce2(float& a, float& b) {
    // 256-thread block; on exit all threads hold the full sums.
    #pragma unroll
    for (int o = 16; o; o >>= 1) {
        a += __shfl_xor_sync(0xffffffffu, a, o);
        b += __shfl_xor_sync(0xffffffffu, b, o);
    }
    __shared__ float sa[8], sb[8];
    int w = threadIdx.x >> 5;
    if ((threadIdx.x & 31) == 0) { sa[w] = a; sb[w] = b; }
    __syncthreads();
    a = sa[threadIdx.x & 7];
    b = sb[threadIdx.x & 7];
    #pragma unroll
    for (int o = 4; o; o >>= 1) {
        a += __shfl_xor_sync(0xffffffffu, a, o);
        b += __shfl_xor_sync(0xffffffffu, b, o);
    }
}

// ---------------- kernels ----------------

// LayerNorm over rows of 256. grid = nrows, block = 256.
__global__ void kLN(const float* __restrict__ x, const float* __restrict__ g,
                    const float* __restrict__ bt, float* __restrict__ y) {
    size_t row = blockIdx.x;
    int i = threadIdx.x;
    float v = x[row * 256 + i];
    float a = v, b = v * v;
    blockReduce2(a, b);
    float m = a * (1.0f / 256.0f);
    float var = b * (1.0f / 256.0f) - m * m;
    float rs = rsqrtf(var + EPSLN);
    y[row * 256 + i] = (v - m) * rs * g[i] + bt[i];
}

// slots = mu + exp(log_sigma) * noise. grid 512, block 256.
__global__ void kInitSlots(const float* __restrict__ noise, const float* __restrict__ mu,
                           const float* __restrict__ ls) {
    int idx = blockIdx.x * 256 + threadIdx.x;
    int d = idx & 255;
    g_slots[idx] = mu[d] + __expf(ls[d]) * noise[idx];
}

// Wqk[j][i] = scale * sum_d Wq[d][j] * Wk[d][i]. grid 256 (j), block 256 (i).
__global__ void kWqk(const float* __restrict__ Wq, const float* __restrict__ Wk) {
    int j = blockIdx.x, i = threadIdx.x;
    float a = 0.f;
    for (int d = 0; d < 256; d++) a += Wq[d * 256 + j] * Wk[d * 256 + i];
    g_Wqk[j * 256 + i] = a * SCALE_;
}

// bqk / wb / c0. grid 2, block 256.
__global__ void kMisc(const float* __restrict__ Wq, const float* __restrict__ Wk,
                      const float* __restrict__ bq, const float* __restrict__ bk) {
    int j = threadIdx.x;
    if (blockIdx.x == 0) {
        float a = 0.f;
        for (int d = 0; d < 256; d++) a += bq[d] * Wk[d * 256 + j];
        g_bqk[j] = a * SCALE_;
        if (j == 0) {
            float c = 0.f;
            for (int d = 0; d < 256; d++) c += bq[d] * bk[d];
            g_c0 = c * SCALE_;
        }
    } else {
        float a = 0.f;
        for (int d = 0; d < 256; d++) a += Wq[d * 256 + j] * bk[d];
        g_wb[j] = a * SCALE_;
    }
}

// transpose src[R][C] -> dst[C][R]. grid (C/32, R/32), block (32, 8).
__global__ void kT(const float* __restrict__ src, float* __restrict__ dst, int R, int C) {
    __shared__ float t[32][33];
    int c = blockIdx.x * 32 + threadIdx.x;
    int r = blockIdx.y * 32 + threadIdx.y;
    #pragma unroll
    for (int k = 0; k < 32; k += 8)
        t[threadIdx.y + k][threadIdx.x] = src[(size_t)(r + k) * C + c];
    __syncthreads();
    int cc = blockIdx.x * 32 + threadIdx.y;
    int rr = blockIdx.y * 32 + threadIdx.x;
    #pragma unroll
    for (int k = 0; k < 32; k += 8)
        dst[(size_t)(cc + k) * R + rr] = t[threadIdx.x][threadIdx.y + k];
}

// qb[r] = sn[r].wb + c0. grid 2, block 256.
__global__ void kQb() {
    int r = blockIdx.x * 256 + threadIdx.x;
    const float* s = g_sn + (size_t)r * 256;
    float a = g_c0;
    for (int i = 0; i < 256; i++) a += s[i] * g_wb[i];
    g_qb[r] = a;
}

// zero S and U. grid 512, block 256.
__global__ void kZeroSU() {
    int idx = blockIdx.x * 256 + threadIdx.x;
    g_U[idx] = 0.f;
    if (idx < BK_) g_S[idx] = 0.f;
}

// dots + softmax over K + S accumulation. grid (16, 64), block 256. one thread per row n.
__global__ void kA(int last, float* __restrict__ out_attn) {
    int b = blockIdx.y;
    int n = blockIdx.x * 256 + threadIdx.x;
    __shared__ __align__(16) float4 sqt[8][64];
    __shared__ float sqb[8];
    const float4* qts = reinterpret_cast<const float4*>(g_qt + (size_t)b * 8 * 256);
    for (int i = threadIdx.x; i < 512; i += 256) (reinterpret_cast<float4*>(sqt))[i] = qts[i];
    if (threadIdx.x < 8) sqb[threadIdx.x] = g_qb[b * 8 + threadIdx.x];
    __syncthreads();

    const float4* xr = reinterpret_cast<const float4*>(g_xn + ((size_t)b * N_ + n) * 256);
    float acc[8];
    #pragma unroll
    for (int k = 0; k < 8; k++) acc[k] = sqb[k];
    #pragma unroll 4
    for (int i4 = 0; i4 < 64; i4++) {
        float4 x4 = xr[i4];
        #pragma unroll
        for (int k = 0; k < 8; k++) {
            float4 q = sqt[k][i4];
            acc[k] += x4.x * q.x + x4.y * q.y + x4.z * q.z + x4.w * q.w;
        }
    }
    float m = acc[0];
    #pragma unroll
    for (int k = 1; k < 8; k++) m = fmaxf(m, acc[k]);
    float e[8], s = 0.f;
    #pragma unroll
    for (int k = 0; k < 8; k++) { e[k] = __expf(acc[k] - m); s += e[k]; }
    float inv = 1.0f / s;
    float a[8];
    #pragma unroll
    for (int k = 0; k < 8; k++) a[k] = e[k] * inv;

    float4* ap = reinterpret_cast<float4*>(g_attn + ((size_t)b * N_ + n) * 8);
    ap[0] = make_float4(a[0], a[1], a[2], a[3]);
    ap[1] = make_float4(a[4], a[5], a[6], a[7]);
    if (last) {
        #pragma unroll
        for (int k = 0; k < 8; k++)
            out_attn[((size_t)b * 8 + k) * N_ + n] = a[k];
    }
    // S accumulation: warp reduce, one atomic per warp per slot
    #pragma unroll
    for (int k = 0; k < 8; k++) {
        float v = a[k];
        #pragma unroll
        for (int o = 16; o; o >>= 1) v += __shfl_xor_sync(0xffffffffu, v, o);
        if ((threadIdx.x & 31) == 0) atomicAdd(&g_S[b * 8 + k], v);
    }
}

// U[b,k,:] += sum_n attn[b,n,k] * xn[b,n,:]. grid (8, 64), block 256 (thread = dim d).
__global__ void kB() {
    int b = blockIdx.y, chunk = blockIdx.x;
    int d = threadIdx.x;
    float u[8] = {0.f, 0.f, 0.f, 0.f, 0.f, 0.f, 0.f, 0.f};
    size_t rowbase = (size_t)b * N_ + (size_t)chunk * 512;
    const float* xp = g_xn + rowbase * 256 + d;
    const float4* ap = reinterpret_cast<const float4*>(g_attn + rowbase * 8);
    for (int n = 0; n < 512; n++) {
        float xv = xp[(size_t)n * 256];
        float4 a0 = ap[n * 2], a1 = ap[n * 2 + 1];
        u[0] += a0.x * xv; u[1] += a0.y * xv; u[2] += a0.z * xv; u[3] += a0.w * xv;
        u[4] += a1.x * xv; u[5] += a1.y * xv; u[6] += a1.z * xv; u[7] += a1.w * xv;
    }
    int r = b * 8;
    #pragma unroll
    for (int k = 0; k < 8; k++) atomicAdd(&g_U[(size_t)(r + k) * 256 + d], u[k]);
}

// un = U/(S+eps), snorm = S/(S+eps). grid 512, block 256.
__global__ void kUnprep() {
    int r = blockIdx.x, i = threadIdx.x;
    float S = g_S[r];
    float inv = 1.0f / (S + EPSA);
    g_un[(size_t)r * 256 + i] = g_U[(size_t)r * 256 + i] * inv;
    if (i == 0) g_snorm[r] = S * inv;
}

// generic small GEMM: out[512][N] = epi( X[512][K] @ Wt[K][N] ), 64x64 tiles.
// mode 0: +bias; 1: relu(+bias); 2: +bias+resid; 3: +auxRow[row]*auxVec[col]
__global__ void kGemm(const float* __restrict__ X, const float* __restrict__ Wt,
                      const float* __restrict__ bias, const float* __restrict__ resid,
                      const float* __restrict__ auxRow, const float* __restrict__ auxVec,
                      float* __restrict__ out, float* __restrict__ out2,
                      int N, int K, int mode) {
    __shared__ __align__(16) float sX[16][68];
    __shared__ __align__(16) float sW[16][68];
    int m0 = blockIdx.y * 64, n0 = blockIdx.x * 64;
    int tx = threadIdx.x & 15, ty = threadIdx.x >> 4;
    float acc[4][4] = {};
    for (int k0 = 0; k0 < K; k0 += 16) {
        #pragma unroll
        for (int e = threadIdx.x; e < 1024; e += 256) {
            int r = e >> 4, kk = e & 15;
            sX[kk][r] = X[(size_t)(m0 + r) * K + k0 + kk];
        }
        #pragma unroll
        for (int e = threadIdx.x; e < 1024; e += 256) {
            int kk = e >> 6, nn = e & 63;
            sW[kk][nn] = Wt[(size_t)(k0 + kk) * N + n0 + nn];
        }
        __syncthreads();
        #pragma unroll
        for (int kk = 0; kk < 16; kk++) {
            float4 a4 = *reinterpret_cast<const float4*>(&sX[kk][ty * 4]);
            float4 b4 = *reinterpret_cast<const float4*>(&sW[kk][tx * 4]);
            float a[4] = {a4.x, a4.y, a4.z, a4.w};
            float bb[4] = {b4.x, b4.y, b4.z, b4.w};
            #pragma unroll
            for (int i = 0; i < 4; i++)
                #pragma unroll
                for (int j = 0; j < 4; j++)
                    acc[i][j] += a[i] * bb[j];
        }
        __syncthreads();
    }
    #pragma unroll
    for (int i = 0; i < 4; i++) {
        int row = m0 + ty * 4 + i;
        #pragma unroll
        for (int j = 0; j < 4; j++) {
            int col = n0 + tx * 4 + j;
            float o = acc[i][j];
            if (bias) o += bias[col];
            if (mode == 1) o = fmaxf(o, 0.f);
            else if (mode == 2) o += resid[(size_t)row * N + col];
            else if (mode == 3) o += auxRow[row] * auxVec[col];
            out[(size_t)row * N + col] = o;
            if (out2) out2[(size_t)row * N + col] = o;
        }
    }
}

// GRU gate combine + ln_ff fused. grid 512, block 256.
__global__ void kE(const float* __restrict__ gff, const float* __restrict__ bff) {
    int r = blockIdx.x, d = threadIdx.x;
    const float* gi = g_gi + (size_t)r * 768;
    const float* gh = g_gh + (size_t)r * 768;
    float ir = gi[d],       hr = gh[d];
    float iz = gi[256 + d], hz = gh[256 + d];
    float in = gi[512 + d], hn = gh[512 + d];
    float rg = 1.0f / (1.0f + __expf(-(ir + hr)));
    float z  = 1.0f / (1.0f + __expf(-(iz + hz)));
    float nn = tanhf(in + rg * hn);
    float hp = g_slots[(size_t)r * 256 + d];
    float h = (1.0f - z) * nn + z * hp;
    g_h[(size_t)r * 256 + d] = h;
    float a = h, b = h * h;
    blockReduce2(a, b);
    float m = a * (1.0f / 256.0f);
    float var = b * (1.0f / 256.0f) - m * m;
    float rs = rsqrtf(var + EPSLN);
    g_ff[(size_t)r * 256 + d] = (h - m) * rs * gff[d] + bff[d];
}

// ---------------- launch ----------------
extern "C" void kernel_launch(void* const* d_in, const int* in_sizes, int n_in,
                              void* d_out, int out_size) {
    (void)in_sizes; (void)n_in; (void)out_size;
    const float* inputs  = (const float*)d_in[0];
    const float* noise   = (const float*)d_in[1];
    const float* slot_mu = (const float*)d_in[2];
    const float* slot_ls = (const float*)d_in[3];
    const float* Wq      = (const float*)d_in[4];
    const float* bq      = (const float*)d_in[5];
    const float* Wk      = (const float*)d_in[6];
    const float* bk      = (const float*)d_in[7];
    const float* Wv      = (const float*)d_in[8];
    const float* bv      = (const float*)d_in[9];
    const float* W_ih    = (const float*)d_in[10];
    const float* b_ih    = (const float*)d_in[11];
    const float* W_hh    = (const float*)d_in[12];
    const float* b_hh    = (const float*)d_in[13];
    const float* ln_in_g = (const float*)d_in[14];
    const float* ln_in_b = (const float*)d_in[15];
    const float* ln_s_g  = (const float*)d_in[16];
    const float* ln_s_b  = (const float*)d_in[17];
    const float* ln_ff_g = (const float*)d_in[18];
    const float* ln_ff_b = (const float*)d_in[19];
    const float* W1      = (const float*)d_in[20];
    const float* b1      = (const float*)d_in[21];
    const float* W2      = (const float*)d_in[22];
    const float* b2      = (const float*)d_in[23];

    float* out = (float*)d_out;
    float* out_slots = out;                  // [B,K,D] = 131072
    float* out_attn  = out + BK_ * D_;       // [B,K,N] = 2097152

    // symbol addresses (capture-safe queries, no allocation)
    float *p_xn, *p_slots, *p_sn, *p_qt, *p_Wqk, *p_bqk, *p_un, *p_snorm, *p_updates;
    float *p_WvT, *p_WihT, *p_WhhT, *p_gi, *p_gh, *p_ff, *p_f1, *p_W1T, *p_W2T, *p_h;
    cudaGetSymbolAddress((void**)&p_xn, g_xn);
    cudaGetSymbolAddress((void**)&p_slots, g_slots);
    cudaGetSymbolAddress((void**)&p_sn, g_sn);
    cudaGetSymbolAddress((void**)&p_qt, g_qt);
    cudaGetSymbolAddress((void**)&p_Wqk, g_Wqk);
    cudaGetSymbolAddress((void**)&p_bqk, g_bqk);
    cudaGetSymbolAddress((void**)&p_un, g_un);
    cudaGetSymbolAddress((void**)&p_snorm, g_snorm);
    cudaGetSymbolAddress((void**)&p_updates, g_updates);
    cudaGetSymbolAddress((void**)&p_WvT, g_WvT);
    cudaGetSymbolAddress((void**)&p_WihT, g_WihT);
    cudaGetSymbolAddress((void**)&p_WhhT, g_WhhT);
    cudaGetSymbolAddress((void**)&p_gi, g_gi);
    cudaGetSymbolAddress((void**)&p_gh, g_gh);
    cudaGetSymbolAddress((void**)&p_ff, g_ff);
    cudaGetSymbolAddress((void**)&p_f1, g_f1);
    cudaGetSymbolAddress((void**)&p_W1T, g_W1T);
    cudaGetSymbolAddress((void**)&p_W2T, g_W2T);
    cudaGetSymbolAddress((void**)&p_h, g_h);

    // ---- one-time prep ----
    kLN<<<B_ * N_, 256>>>(inputs, ln_in_g, ln_in_b, p_xn);
    kInitSlots<<<BK_, 256>>>(noise, slot_mu, slot_ls);
    kWqk<<<256, 256>>>(Wq, Wk);
    kMisc<<<2, 256>>>(Wq, Wk, bq, bk);
    kT<<<dim3(256 / 32, 768 / 32), dim3(32, 8)>>>(W_ih, p_WihT, 768, 256);
    kT<<<dim3(256 / 32, 768 / 32), dim3(32, 8)>>>(W_hh, p_WhhT, 768, 256);
    kT<<<dim3(256 / 32, 256 / 32), dim3(32, 8)>>>(Wv, p_WvT, 256, 256);
    kT<<<dim3(256 / 32, 512 / 32), dim3(32, 8)>>>(W1, p_W1T, 512, 256);
    kT<<<dim3(512 / 32, 256 / 32), dim3(32, 8)>>>(W2, p_W2T, 256, 512);

    // ---- 3 slot-attention iterations ----
    for (int it = 0; it < 3; it++) {
        int last = (it == 2);
        kLN<<<BK_, 256>>>(p_slots, ln_s_g, ln_s_b, p_sn);
        // qt = sn @ Wqk + bqk (scale folded in)
        kGemm<<<dim3(4, 8), 256>>>(p_sn, p_Wqk, p_bqk, nullptr, nullptr, nullptr,
                                   p_qt, nullptr, 256, 256, 0);
        kQb<<<2, 256>>>();
        kZeroSU<<<512, 256>>>();
        kA<<<dim3(16, 64), 256>>>(last, out_attn);
        kB<<<dim3(8, 64), 256>>>();
        kUnprep<<<512, 256>>>();
        // updates = un @ Wv^T + snorm*bv
        kGemm<<<dim3(4, 8), 256>>>(p_un, p_WvT, nullptr, nullptr, p_snorm, bv,
                                   p_updates, nullptr, 256, 256, 3);
        // GRU gates
        kGemm<<<dim3(12, 8), 256>>>(p_updates, p_WihT, b_ih, nullptr, nullptr, nullptr,
                                    p_gi, nullptr, 768, 256, 0);
        kGemm<<<dim3(12, 8), 256>>>(p_slots, p_WhhT, b_hh, nullptr, nullptr, nullptr,
                                    p_gh, nullptr, 768, 256, 0);
        kE<<<BK_, 256>>>(ln_ff_g, ln_ff_b);
        // FF
        kGemm<<<dim3(8, 8), 256>>>(p_ff, p_W1T, b1, nullptr, nullptr, nullptr,
                                   p_f1, nullptr, 512, 256, 1);
        // slots = h + f1 @ W2^T + b2   (also written to d_out on last iter)
        kGemm<<<dim3(4, 8), 256>>>(p_f1, p_W2T, b2, p_h, nullptr, nullptr,
                                   p_slots, last ? out_slots : nullptr, 256, 512, 2);
    }
}

// round 4
// speedup vs baseline: 1.3539x; 1.3539x over previous
#include <cuda_runtime.h>
#include <math.h>
#include <stdint.h>
#include <stddef.h>

// ---------------- problem dims ----------------
#define B_    64
#define N_    4096
#define DIN_  256
#define K_    8
#define D_    256
#define H_    512
#define BK_   512
#define SCALE_ 0.0625f
#define EPSLN 1e-5f
#define EPSA  1e-8f

typedef unsigned long long u64;

// ---------------- device scratch ----------------
__device__ __align__(16) float g_slots[BK_ * D_];
__device__ __align__(16) float g_sn[BK_ * D_];
__device__ __align__(16) float g_qt[BK_ * D_];
__device__ __align__(16) float g_gq[BK_ * D_];      // g ⊙ qt
__device__ float g_C1[BK_];
__device__ float g_C2[BK_];
__device__ __align__(16) float g_P[BK_ * D_];       // Σ a*rs*v
__device__ float g_SA[BK_];
__device__ float g_SW[BK_];
__device__ __align__(16) float g_un[BK_ * D_];
__device__ float g_snorm[BK_];
__device__ __align__(16) float g_updates[BK_ * D_];
__device__ __align__(16) float g_gi[BK_ * 3 * D_];
__device__ __align__(16) float g_gh[BK_ * 3 * D_];
__device__ __align__(16) float g_h[BK_ * D_];
__device__ __align__(16) float g_ff[BK_ * D_];
__device__ __align__(16) float g_f1[BK_ * H_];
__device__ __align__(16) float g_Wqk[D_ * D_];
__device__ float g_bqk[D_];
__device__ float g_wb[D_];
__device__ float g_c0;
__device__ __align__(16) float g_WihT[D_ * 3 * D_];
__device__ __align__(16) float g_WhhT[D_ * 3 * D_];
__device__ __align__(16) float g_WvT[D_ * D_];
__device__ __align__(16) float g_W1T[D_ * H_];
__device__ __align__(16) float g_W2T[H_ * D_];

// ---------------- f32x2 packed helpers ----------------
__device__ __forceinline__ u64 pk2(float x, float y) {
    u64 r; asm("mov.b64 %0, {%1, %2};" : "=l"(r) : "f"(x), "f"(y)); return r;
}
__device__ __forceinline__ void upk2(u64 v, float& x, float& y) {
    asm("mov.b64 {%0, %1}, %2;" : "=f"(x), "=f"(y) : "l"(v));
}
__device__ __forceinline__ void fma2(u64& d, u64 a, u64 b) {
    asm("fma.rn.f32x2 %0, %1, %2, %0;" : "+l"(d) : "l"(a), "l"(b));
}

// ---------------- block reduce (2 values, 256 threads) ----------------
__device__ __forceinline__ void blockReduce2(float& a, float& b) {
    #pragma unroll
    for (int o = 16; o; o >>= 1) {
        a += __shfl_xor_sync(0xffffffffu, a, o);
        b += __shfl_xor_sync(0xffffffffu, b, o);
    }
    __shared__ float sa[8], sb[8];
    __syncthreads();   // safe for repeated calls
    int w = threadIdx.x >> 5;
    if ((threadIdx.x & 31) == 0) { sa[w] = a; sb[w] = b; }
    __syncthreads();
    a = sa[threadIdx.x & 7];
    b = sb[threadIdx.x & 7];
    #pragma unroll
    for (int o = 4; o; o >>= 1) {
        a += __shfl_xor_sync(0xffffffffu, a, o);
        b += __shfl_xor_sync(0xffffffffu, b, o);
    }
}

// ---------------- small kernels ----------------
__global__ void kLN(const float* __restrict__ x, const float* __restrict__ g,
                    const float* __restrict__ bt, float* __restrict__ y) {
    size_t row = blockIdx.x;
    int i = threadIdx.x;
    float v = x[row * 256 + i];
    float a = v, b = v * v;
    blockReduce2(a, b);
    float m = a * (1.0f / 256.0f);
    float var = b * (1.0f / 256.0f) - m * m;
    float rs = rsqrtf(var + EPSLN);
    y[row * 256 + i] = (v - m) * rs * g[i] + bt[i];
}

__global__ void kInitSlots(const float* __restrict__ noise, const float* __restrict__ mu,
                           const float* __restrict__ ls) {
    int idx = blockIdx.x * 256 + threadIdx.x;
    int d = idx & 255;
    g_slots[idx] = mu[d] + __expf(ls[d]) * noise[idx];
}

// Wqk[j][i] = scale * sum_d Wq[d][j]*Wk[d][i]. grid 256, block 256.
__global__ void kWqk(const float* __restrict__ Wq, const float* __restrict__ Wk) {
    int j = blockIdx.x, i = threadIdx.x;
    float a0 = 0.f, a1 = 0.f, a2 = 0.f, a3 = 0.f;
    #pragma unroll 4
    for (int d = 0; d < 256; d += 4) {
        a0 = fmaf(Wq[(d + 0) * 256 + j], Wk[(d + 0) * 256 + i], a0);
        a1 = fmaf(Wq[(d + 1) * 256 + j], Wk[(d + 1) * 256 + i], a1);
        a2 = fmaf(Wq[(d + 2) * 256 + j], Wk[(d + 2) * 256 + i], a2);
        a3 = fmaf(Wq[(d + 3) * 256 + j], Wk[(d + 3) * 256 + i], a3);
    }
    g_Wqk[j * 256 + i] = (a0 + a1 + a2 + a3) * SCALE_;
}

__global__ void kZeroMisc() {
    int j = threadIdx.x;
    if (blockIdx.x == 0) { g_bqk[j] = 0.f; if (j == 0) g_c0 = 0.f; }
    else g_wb[j] = 0.f;
}

// grid (3, 8), block 256. partial over d in [y*32, y*32+32).
__global__ void kMisc(const float* __restrict__ Wq, const float* __restrict__ Wk,
                      const float* __restrict__ bq, const float* __restrict__ bk) {
    int j = threadIdx.x;
    int d0 = blockIdx.y * 32;
    if (blockIdx.x == 0) {
        float a = 0.f;
        #pragma unroll 4
        for (int d = d0; d < d0 + 32; d++) a = fmaf(bq[d], Wk[d * 256 + j], a);
        atomicAdd(&g_bqk[j], a * SCALE_);
    } else if (blockIdx.x == 1) {
        float a = 0.f;
        #pragma unroll 4
        for (int d = d0; d < d0 + 32; d++) a = fmaf(Wq[d * 256 + j], bk[d], a);
        atomicAdd(&g_wb[j], a * SCALE_);
    } else {
        if (j < 32) {
            float a = bq[d0 + j] * bk[d0 + j];
            #pragma unroll
            for (int o = 16; o; o >>= 1) a += __shfl_xor_sync(0xffffffffu, a, o);
            if (j == 0) atomicAdd(&g_c0, a * SCALE_);
        }
    }
}

// transpose src[R][C] -> dst[C][R]
__global__ void kT(const float* __restrict__ src, float* __restrict__ dst, int R, int C) {
    __shared__ float t[32][33];
    int c = blockIdx.x * 32 + threadIdx.x;
    int r = blockIdx.y * 32 + threadIdx.y;
    #pragma unroll
    for (int k = 0; k < 32; k += 8)
        t[threadIdx.y + k][threadIdx.x] = src[(size_t)(r + k) * C + c];
    __syncthreads();
    int cc = blockIdx.x * 32 + threadIdx.y;
    int rr = blockIdx.y * 32 + threadIdx.x;
    #pragma unroll
    for (int k = 0; k < 32; k += 8)
        dst[(size_t)(cc + k) * R + rr] = t[threadIdx.x][threadIdx.y + k];
}

// per-iteration prep: gq = g*qt, C1 = sum(gq), C2 = sum(qt*b) + sn.wb + c0. grid 512, block 256.
__global__ void kPrep(const float* __restrict__ gg, const float* __restrict__ gb) {
    int r = blockIdx.x, i = threadIdx.x;
    float qt = g_qt[(size_t)r * 256 + i];
    float gq = gg[i] * qt;
    g_gq[(size_t)r * 256 + i] = gq;
    float c1 = gq, c2 = qt * gb[i];
    blockReduce2(c1, c2);
    float qb = g_sn[(size_t)r * 256 + i] * g_wb[i], dm = 0.f;
    blockReduce2(qb, dm);
    if (i == 0) { g_C1[r] = c1; g_C2[r] = c2 + qb + g_c0; }
}

__global__ void kZeroP() {
    int idx = blockIdx.x * 256 + threadIdx.x;
    g_P[idx] = 0.f;
    if (idx < BK_) { g_SA[idx] = 0.f; g_SW[idx] = 0.f; }
}

// ============ FUSED: LN + dots + softmax + P/SA/SW accumulation ============
// grid (16, 64), block 128 (4 warps). Each warp: 64 consecutive rows.
__global__ void __launch_bounds__(128) kFA(const float* __restrict__ inputs,
                                           int last, float* __restrict__ out_attn) {
    int b = blockIdx.y;
    int warp = threadIdx.x >> 5, lane = threadIdx.x & 31;
    int row0 = blockIdx.x * 256 + warp * 64;
    int r8 = b * 8;

    // persistent gq registers: lane owns dims {4l..4l+3, 128+4l..128+4l+3}
    u64 gq[8][4];
    float C1[8], C2[8];
    #pragma unroll
    for (int k = 0; k < 8; k++) {
        const float* gp = g_gq + (size_t)(r8 + k) * 256;
        float2 q0 = *(const float2*)(gp + 4 * lane);
        float2 q1 = *(const float2*)(gp + 4 * lane + 2);
        float2 q2 = *(const float2*)(gp + 128 + 4 * lane);
        float2 q3 = *(const float2*)(gp + 128 + 4 * lane + 2);
        gq[k][0] = pk2(q0.x, q0.y); gq[k][1] = pk2(q1.x, q1.y);
        gq[k][2] = pk2(q2.x, q2.y); gq[k][3] = pk2(q3.x, q3.y);
        C1[k] = g_C1[r8 + k]; C2[k] = g_C2[r8 + k];
    }
    u64 zero2 = pk2(0.f, 0.f);
    u64 P[8][4];
    #pragma unroll
    for (int k = 0; k < 8; k++) { P[k][0] = zero2; P[k][1] = zero2; P[k][2] = zero2; P[k][3] = zero2; }
    float SA[8] = {0.f, 0.f, 0.f, 0.f, 0.f, 0.f, 0.f, 0.f};
    float SW[8] = {0.f, 0.f, 0.f, 0.f, 0.f, 0.f, 0.f, 0.f};

    const float4* vp = (const float4*)(inputs + ((size_t)b * N_ + row0) * 256);
    float4 a0 = vp[lane], a1 = vp[lane + 32];

    for (int r = 0; r < 64; r++) {
        int n = row0 + r;
        // prefetch next row
        float4 b0, b1;
        if (r < 63) {
            const float4* vn = vp + (size_t)(r + 1) * 64;
            b0 = vn[lane]; b1 = vn[lane + 32];
        }
        // LN stats
        float s  = ((a0.x + a0.y) + (a0.z + a0.w)) + ((a1.x + a1.y) + (a1.z + a1.w));
        float ss = fmaf(a0.x, a0.x, fmaf(a0.y, a0.y, fmaf(a0.z, a0.z, fmaf(a0.w, a0.w,
                   fmaf(a1.x, a1.x, fmaf(a1.y, a1.y, fmaf(a1.z, a1.z, a1.w * a1.w)))))));
        #pragma unroll
        for (int o = 16; o; o >>= 1) {
            s  += __shfl_xor_sync(0xffffffffu, s, o);
            ss += __shfl_xor_sync(0xffffffffu, ss, o);
        }
        float m  = s * (1.0f / 256.0f);
        float var = fmaf(ss, 1.0f / 256.0f, -m * m);
        float rs = rsqrtf(var + EPSLN);
        float w  = m * rs;

        u64 x01 = pk2(a0.x, a0.y), x23 = pk2(a0.z, a0.w);
        u64 x45 = pk2(a1.x, a1.y), x67 = pk2(a1.z, a1.w);

        // dots (packed)
        float dt[8];
        #pragma unroll
        for (int k = 0; k < 8; k++) {
            u64 d2 = zero2;
            fma2(d2, x01, gq[k][0]); fma2(d2, x23, gq[k][1]);
            fma2(d2, x45, gq[k][2]); fma2(d2, x67, gq[k][3]);
            float lo, hi; upk2(d2, lo, hi);
            dt[k] = lo + hi;
        }
        #pragma unroll
        for (int o = 16; o; o >>= 1)
            #pragma unroll
            for (int k = 0; k < 8; k++) dt[k] += __shfl_xor_sync(0xffffffffu, dt[k], o);

        // logits + softmax over 8 slots
        float lg[8];
        #pragma unroll
        for (int k = 0; k < 8; k++) lg[k] = fmaf(rs, dt[k], fmaf(-w, C1[k], C2[k]));
        float mx = lg[0];
        #pragma unroll
        for (int k = 1; k < 8; k++) mx = fmaxf(mx, lg[k]);
        float ak[8], esum = 0.f;
        #pragma unroll
        for (int k = 0; k < 8; k++) { ak[k] = __expf(lg[k] - mx); esum += ak[k]; }
        float inv = __fdividef(1.0f, esum);
        #pragma unroll
        for (int k = 0; k < 8; k++) ak[k] *= inv;

        if (last) {
            #pragma unroll
            for (int k = 0; k < 8; k++)
                if (lane == k) out_attn[(size_t)(r8 + k) * N_ + n] = ak[k];
        }

        // accumulate P, SA, SW
        #pragma unroll
        for (int k = 0; k < 8; k++) {
            float ar = ak[k] * rs;
            u64 ap = pk2(ar, ar);
            fma2(P[k][0], ap, x01); fma2(P[k][1], ap, x23);
            fma2(P[k][2], ap, x45); fma2(P[k][3], ap, x67);
            SA[k] += ak[k];
            SW[k] = fmaf(ak[k], w, SW[k]);
        }
        a0 = b0; a1 = b1;
    }

    // flush
    #pragma unroll
    for (int k = 0; k < 8; k++) {
        float* Pg = g_P + (size_t)(r8 + k) * 256;
        float x, y;
        upk2(P[k][0], x, y); atomicAdd(Pg + 4 * lane, x);       atomicAdd(Pg + 4 * lane + 1, y);
        upk2(P[k][1], x, y); atomicAdd(Pg + 4 * lane + 2, x);   atomicAdd(Pg + 4 * lane + 3, y);
        upk2(P[k][2], x, y); atomicAdd(Pg + 128 + 4 * lane, x); atomicAdd(Pg + 128 + 4 * lane + 1, y);
        upk2(P[k][3], x, y); atomicAdd(Pg + 128 + 4 * lane + 2, x); atomicAdd(Pg + 128 + 4 * lane + 3, y);
    }
    if (lane == 0) {
        #pragma unroll
        for (int k = 0; k < 8; k++) {
            atomicAdd(&g_SA[r8 + k], SA[k]);
            atomicAdd(&g_SW[r8 + k], SW[k]);
        }
    }
}

// un = (g*(P - SW) + b*SA) / (SA+eps); snorm = SA/(SA+eps). grid 512, block 256.
__global__ void kUnprep(const float* __restrict__ gg, const float* __restrict__ gb) {
    int r = blockIdx.x, i = threadIdx.x;
    float S = g_SA[r], w = g_SW[r];
    float inv = 1.0f / (S + EPSA);
    float Pv = g_P[(size_t)r * 256 + i];
    g_un[(size_t)r * 256 + i] = (gg[i] * (Pv - w) + gb[i] * S) * inv;
    if (i == 0) g_snorm[r] = S * inv;
}

// ---------------- small GEMM tile (64x64, 256 threads) ----------------
__device__ __forceinline__ void gemmTile(const float* __restrict__ X, const float* __restrict__ Wt,
                                         const float* __restrict__ bias, const float* __restrict__ resid,
                                         const float* __restrict__ auxRow, const float* __restrict__ auxVec,
                                         float* __restrict__ out, float* __restrict__ out2,
                                         int N, int K, int mode) {
    __shared__ __align__(16) float sX[16][68];
    __shared__ __align__(16) float sW[16][68];
    int m0 = blockIdx.y * 64, n0 = blockIdx.x * 64;
    int tx = threadIdx.x & 15, ty = threadIdx.x >> 4;
    float acc[4][4] = {};
    for (int k0 = 0; k0 < K; k0 += 16) {
        #pragma unroll
        for (int e = threadIdx.x; e < 1024; e += 256) {
            int r = e >> 4, kk = e & 15;
            sX[kk][r] = X[(size_t)(m0 + r) * K + k0 + kk];
        }
        #pragma unroll
        for (int e = threadIdx.x; e < 1024; e += 256) {
            int kk = e >> 6, nn = e & 63;
            sW[kk][nn] = Wt[(size_t)(k0 + kk) * N + n0 + nn];
        }
        __syncthreads();
        #pragma unroll
        for (int kk = 0; kk < 16; kk++) {
            float4 a4 = *reinterpret_cast<const float4*>(&sX[kk][ty * 4]);
            float4 b4 = *reinterpret_cast<const float4*>(&sW[kk][tx * 4]);
            float a[4] = {a4.x, a4.y, a4.z, a4.w};
            float bb[4] = {b4.x, b4.y, b4.z, b4.w};
            #pragma unroll
            for (int i = 0; i < 4; i++)
                #pragma unroll
                for (int j = 0; j < 4; j++)
                    acc[i][j] = fmaf(a[i], bb[j], acc[i][j]);
        }
        __syncthreads();
    }
    #pragma unroll
    for (int i = 0; i < 4; i++) {
        int row = m0 + ty * 4 + i;
        #pragma unroll
        for (int j = 0; j < 4; j++) {
            int col = n0 + tx * 4 + j;
            float o = acc[i][j];
            if (bias) o += bias[col];
            if (mode == 1) o = fmaxf(o, 0.f);
            else if (mode == 2) o += resid[(size_t)row * N + col];
            else if (mode == 3) o += auxRow[row] * auxVec[col];
            out[(size_t)row * N + col] = o;
            if (out2) out2[(size_t)row * N + col] = o;
        }
    }
}

__global__ void kGemm(const float* __restrict__ X, const float* __restrict__ Wt,
                      const float* __restrict__ bias, const float* __restrict__ resid,
                      const float* __restrict__ auxRow, const float* __restrict__ auxVec,
                      float* __restrict__ out, float* __restrict__ out2,
                      int N, int K, int mode) {
    gemmTile(X, Wt, bias, resid, auxRow, auxVec, out, out2, N, K, mode);
}

// GRU's two gate GEMMs in one launch (z selects).
__global__ void kGemmGRU(const float* __restrict__ b_ih, const float* __restrict__ b_hh) {
    if (blockIdx.z == 0)
        gemmTile(g_updates, g_WihT, b_ih, nullptr, nullptr, nullptr, g_gi, nullptr, 768, 256, 0);
    else
        gemmTile(g_slots, g_WhhT, b_hh, nullptr, nullptr, nullptr, g_gh, nullptr, 768, 256, 0);
}

// GRU combine + ln_ff fused. grid 512, block 256.
__global__ void kE(const float* __restrict__ gff, const float* __restrict__ bff) {
    int r = blockIdx.x, d = threadIdx.x;
    const float* gi = g_gi + (size_t)r * 768;
    const float* gh = g_gh + (size_t)r * 768;
    float ir = gi[d],       hr = gh[d];
    float iz = gi[256 + d], hz = gh[256 + d];
    float in = gi[512 + d], hn = gh[512 + d];
    float rg = 1.0f / (1.0f + __expf(-(ir + hr)));
    float z  = 1.0f / (1.0f + __expf(-(iz + hz)));
    float nn = tanhf(in + rg * hn);
    float hp = g_slots[(size_t)r * 256 + d];
    float h = (1.0f - z) * nn + z * hp;
    g_h[(size_t)r * 256 + d] = h;
    float a = h, b = h * h;
    blockReduce2(a, b);
    float m = a * (1.0f / 256.0f);
    float var = b * (1.0f / 256.0f) - m * m;
    float rs = rsqrtf(var + EPSLN);
    g_ff[(size_t)r * 256 + d] = (h - m) * rs * gff[d] + bff[d];
}

// ---------------- launch ----------------
extern "C" void kernel_launch(void* const* d_in, const int* in_sizes, int n_in,
                              void* d_out, int out_size) {
    (void)in_sizes; (void)n_in; (void)out_size;
    const float* inputs  = (const float*)d_in[0];
    const float* noise   = (const float*)d_in[1];
    const float* slot_mu = (const float*)d_in[2];
    const float* slot_ls = (const float*)d_in[3];
    const float* Wq      = (const float*)d_in[4];
    const float* bq      = (const float*)d_in[5];
    const float* Wk      = (const float*)d_in[6];
    const float* bk      = (const float*)d_in[7];
    const float* Wv      = (const float*)d_in[8];
    const float* bv      = (const float*)d_in[9];
    const float* W_ih    = (const float*)d_in[10];
    const float* b_ih    = (const float*)d_in[11];
    const float* W_hh    = (const float*)d_in[12];
    const float* b_hh    = (const float*)d_in[13];
    const float* ln_in_g = (const float*)d_in[14];
    const float* ln_in_b = (const float*)d_in[15];
    const float* ln_s_g  = (const float*)d_in[16];
    const float* ln_s_b  = (const float*)d_in[17];
    const float* ln_ff_g = (const float*)d_in[18];
    const float* ln_ff_b = (const float*)d_in[19];
    const float* W1      = (const float*)d_in[20];
    const float* b1      = (const float*)d_in[21];
    const float* W2      = (const float*)d_in[22];
    const float* b2      = (const float*)d_in[23];

    float* out = (float*)d_out;
    float* out_slots = out;
    float* out_attn  = out + BK_ * D_;

    float *p_slots, *p_sn, *p_qt, *p_Wqk, *p_bqk, *p_un, *p_snorm, *p_updates;
    float *p_WvT, *p_WihT, *p_WhhT, *p_ff, *p_f1, *p_W1T, *p_W2T, *p_h;
    cudaGetSymbolAddress((void**)&p_slots, g_slots);
    cudaGetSymbolAddress((void**)&p_sn, g_sn);
    cudaGetSymbolAddress((void**)&p_qt, g_qt);
    cudaGetSymbolAddress((void**)&p_Wqk, g_Wqk);
    cudaGetSymbolAddress((void**)&p_bqk, g_bqk);
    cudaGetSymbolAddress((void**)&p_un, g_un);
    cudaGetSymbolAddress((void**)&p_snorm, g_snorm);
    cudaGetSymbolAddress((void**)&p_updates, g_updates);
    cudaGetSymbolAddress((void**)&p_WvT, g_WvT);
    cudaGetSymbolAddress((void**)&p_WihT, g_WihT);
    cudaGetSymbolAddress((void**)&p_WhhT, g_WhhT);
    cudaGetSymbolAddress((void**)&p_ff, g_ff);
    cudaGetSymbolAddress((void**)&p_f1, g_f1);
    cudaGetSymbolAddress((void**)&p_W1T, g_W1T);
    cudaGetSymbolAddress((void**)&p_W2T, g_W2T);
    cudaGetSymbolAddress((void**)&p_h, g_h);

    // ---- one-time prep ----
    kInitSlots<<<BK_, 256>>>(noise, slot_mu, slot_ls);
    kWqk<<<256, 256>>>(Wq, Wk);
    kZeroMisc<<<2, 256>>>();
    kMisc<<<dim3(3, 8), 256>>>(Wq, Wk, bq, bk);
    kT<<<dim3(8, 24), dim3(32, 8)>>>(W_ih, p_WihT, 768, 256);
    kT<<<dim3(8, 24), dim3(32, 8)>>>(W_hh, p_WhhT, 768, 256);
    kT<<<dim3(8, 8),  dim3(32, 8)>>>(Wv, p_WvT, 256, 256);
    kT<<<dim3(8, 16), dim3(32, 8)>>>(W1, p_W1T, 512, 256);
    kT<<<dim3(16, 8), dim3(32, 8)>>>(W2, p_W2T, 256, 512);

    // ---- 3 slot-attention iterations ----
    for (int it = 0; it < 3; it++) {
        int last = (it == 2);
        kLN<<<BK_, 256>>>(p_slots, ln_s_g, ln_s_b, p_sn);
        kGemm<<<dim3(4, 8), 256>>>(p_sn, p_Wqk, p_bqk, nullptr, nullptr, nullptr,
                                   p_qt, nullptr, 256, 256, 0);
        kPrep<<<BK_, 256>>>(ln_in_g, ln_in_b);
        kZeroP<<<512, 256>>>();
        kFA<<<dim3(16, 64), 128>>>(inputs, last, out_attn);
        kUnprep<<<BK_, 256>>>(ln_in_g, ln_in_b);
        kGemm<<<dim3(4, 8), 256>>>(p_un, p_WvT, nullptr, nullptr, p_snorm, bv,
                                   p_updates, nullptr, 256, 256, 3);
        kGemmGRU<<<dim3(12, 8, 2), 256>>>(b_ih, b_hh);
        kE<<<BK_, 256>>>(ln_ff_g, ln_ff_b);
        kGemm<<<dim3(8, 8), 256>>>(p_ff, p_W1T, b1, nullptr, nullptr, nullptr,
                                   p_f1, nullptr, 512, 256, 1);
        kGemm<<<dim3(4, 8), 256>>>(p_f1, p_W2T, b2, p_h, nullptr, nullptr,
                                   p_slots, last ? out_slots : nullptr, 256, 512, 2);
    }
}